// round 13
// baseline (speedup 1.0000x reference)
#include <cuda_runtime.h>
#include <cuda_bf16.h>
#include <cstdint>

// ============================================================================
// YukarinSa f0 predictor: table-folded encoder + persistent-grid GRU scan.
//
// Round 13: R11 (best, 16.09ms) with the second __syncthreads SPLIT into
// bar.arrive(after dots) / bar.sync(before h_s overwrite), and the poll
// moved BEFORE the sync (into registers). Gate math + h store no longer
// wait for sibling warps' dots; the poll overlaps the previous step's
// tail. Arithmetic and memory ops bit-identical to R11.
// ============================================================================

#define L_STEPS 8192
#define NCTA    128

typedef unsigned long long ull;

__device__ ull      g_ht[2][1024];    // {tag<<32 | f32bits}, one h element per word
__device__ float    g_U[51 * 1024];   // [p][i]
__device__ float    g_V[3072 * 51];   // [r][col]: 0..45=T, 46..49=A, 50=c0
__device__ unsigned g_rec[L_STEPS];

// ---------------------------------------------------------------- PTX helpers
__device__ __forceinline__ ull ffma2(ull a, ull b, ull c) {
    ull d;
    asm("fma.rn.f32x2 %0, %1, %2, %3;" : "=l"(d) : "l"(a), "l"(b), "l"(c));
    return d;
}
__device__ __forceinline__ ull ld_rlx64(const ull* p) {
    ull v;
    asm volatile("ld.relaxed.gpu.global.b64 %0, [%1];" : "=l"(v) : "l"(p));
    return v;
}
__device__ __forceinline__ void st_rlx64(ull* p, ull v) {
    asm volatile("st.relaxed.gpu.global.b64 [%0], %1;" :: "l"(p), "l"(v) : "memory");
}
__device__ __forceinline__ void bar_arrive_1_512() {
    asm volatile("bar.arrive 1, 512;" ::: "memory");
}
__device__ __forceinline__ void bar_sync_1_512() {
    asm volatile("bar.sync 1, 512;" ::: "memory");
}
__device__ __forceinline__ float fast_sig(float x) {
    float e = __expf(-x);
    return __fdividef(1.f, 1.f + e);
}
__device__ __forceinline__ float fast_tanh(float x) {
    float e = __expf(2.f * x);
    return 1.f - __fdividef(2.f, e + 1.f);
}

union F2u { ull u; float2 f; };

// ---------------------------------------------------------------- K0: pack/reset
__global__ void k0_pack(const int* __restrict__ v, const int* __restrict__ c,
                        const int* __restrict__ sa, const int* __restrict__ ea,
                        const int* __restrict__ sap, const int* __restrict__ eap) {
    int i = blockIdx.x * 256 + threadIdx.x;
    if (i < L_STEPS) {
        unsigned r = (unsigned)(v[i] + 1) | ((unsigned)(c[i] + 1) << 8)
                   | ((unsigned)(sa[i]  & 1) << 16) | ((unsigned)(ea[i]  & 1) << 17)
                   | ((unsigned)(sap[i] & 1) << 18) | ((unsigned)(eap[i] & 1) << 19);
        g_rec[i] = r;
        if (i < 1024) {
            g_ht[0][i] = 0ull;                       // tag 0, value 0.0f
            g_ht[1][i] = 0xFFFFFFFF00000000ull;      // never-matching tag
        }
    }
}

// ---------------------------------------------------------------- K1a: U fold
__global__ void k1a_U(const float* __restrict__ encW, const float* __restrict__ encb,
                      const float* __restrict__ emb,  const float* __restrict__ spkemb,
                      const int* __restrict__ sid) {
    __shared__ float ew[516];
    int i = blockIdx.x;
    int tid = threadIdx.x;
    for (int n = tid; n < 516; n += 64) ew[n] = encW[i * 516 + n];
    __syncthreads();
    if (tid < 46) {
        const float* er = emb + tid * 256;
        float s = 0.f;
        for (int e = 0; e < 256; ++e) s = fmaf(ew[e], er[e], s);
        g_U[tid * 1024 + i] = s;
    } else if (tid < 50) {
        g_U[tid * 1024 + i] = ew[256 + (tid - 46)];
    } else if (tid == 50) {
        const float* sr = spkemb + (size_t)sid[0] * 256;
        float s = encb[i];
        for (int e = 0; e < 256; ++e) s = fmaf(ew[260 + e], sr[e], s);
        g_U[50 * 1024 + i] = s;
    }
}

// ---------------------------------------------------------------- K1b: V = Wih_h @ U
__global__ void k1b_V(const float* __restrict__ Wih) {
    __shared__ float Ws[32][129];
    __shared__ float Us[56][128];
    int tid = threadIdx.x;
    int r = tid & 31, pg = tid >> 5;
    int R0 = blockIdx.x * 32;
    float acc[7] = {0.f, 0.f, 0.f, 0.f, 0.f, 0.f, 0.f};
    for (int k0 = 0; k0 < 1024; k0 += 128) {
        for (int n = tid; n < 32 * 128; n += 256) {
            int rr = n >> 7, cc = n & 127;
            Ws[rr][cc] = Wih[(size_t)(R0 + rr) * 1025 + k0 + cc];
        }
        for (int n = tid; n < 56 * 128; n += 256) {
            int pp = n >> 7, cc = n & 127;
            Us[pp][cc] = (pp < 51) ? g_U[pp * 1024 + k0 + cc] : 0.f;
        }
        __syncthreads();
        #pragma unroll 4
        for (int kk = 0; kk < 128; ++kk) {
            float wv = Ws[r][kk];
            #pragma unroll
            for (int j = 0; j < 7; ++j)
                acc[j] = fmaf(wv, Us[pg + 8 * j][kk], acc[j]);
        }
        __syncthreads();
    }
    #pragma unroll
    for (int j = 0; j < 7; ++j) {
        int p = pg + 8 * j;
        if (p < 51) g_V[(size_t)(R0 + r) * 51 + p] = acc[j];
    }
}

// ---------------------------------------------------------------- K3: persistent scan
__global__ void __launch_bounds__(256, 1)
k3_scan(const float* __restrict__ Wih, const float* __restrict__ Whh,
        const float* __restrict__ bih, const float* __restrict__ bhh,
        const float* __restrict__ postW, const float* __restrict__ postb,
        float* __restrict__ out) {
    __shared__ unsigned rec_s[L_STEPS];
    __shared__ __align__(16) float h_s[1024];
    __shared__ float Ts[3][8][46];
    __shared__ float Ac[3][8][16];

    const int tid  = threadIdx.x;
    const int w    = tid >> 5;
    const int lane = tid & 31;
    const int cta  = blockIdx.x;
    const int d    = cta * 8 + w;          // owned h-dim

    // --- register-resident weight pairs, R3 strided layout:
    //     wr[k] at ull index lane+32k covers h floats 2*lane+64k, +1
    ull wr[16], wz[16], wn[16], wp[16];
    {
        const ull* pr = (const ull*)(Whh + (size_t)d          * 1024) + lane;
        const ull* pz = (const ull*)(Whh + (size_t)(1024 + d) * 1024) + lane;
        const ull* pn = (const ull*)(Whh + (size_t)(2048 + d) * 1024) + lane;
        const ull* pp = (const ull*)(postW) + lane;
        #pragma unroll
        for (int k = 0; k < 16; ++k) {
            wr[k] = pr[32 * k]; wz[k] = pz[32 * k];
            wn[k] = pn[32 * k]; wp[k] = pp[32 * k];
        }
    }
    const float b_r  = bhh[d], b_z = bhh[1024 + d], b_n = bhh[2048 + d];
    const float wf0r = Wih[(size_t)d          * 1025 + 1024];
    const float wf0z = Wih[(size_t)(1024 + d) * 1025 + 1024];
    const float wf0n = Wih[(size_t)(2048 + d) * 1025 + 1024];
    const float pb   = postb[0];

    // --- shared tables ---
    for (int n = tid; n < L_STEPS; n += 256) rec_s[n] = g_rec[n];
    for (int n = tid; n < 3 * 8 * 46; n += 256) {
        int g = n / 368, rm = n - g * 368, w2 = rm / 46, p = rm - w2 * 46;
        Ts[g][w2][p] = g_V[(size_t)(cta * 8 + w2 + g * 1024) * 51 + p];
    }
    #pragma unroll
    for (int g = 0; g < 3; ++g) {
        int r = d + g * 1024;
        if (lane < 16) {
            float val = g_V[(size_t)r * 51 + 50] + bih[r];
            if (lane & 1) val += g_V[(size_t)r * 51 + 46];
            if (lane & 2) val += g_V[(size_t)r * 51 + 47];
            if (lane & 4) val += g_V[(size_t)r * 51 + 48];
            if (lane & 8) val += g_V[(size_t)r * 51 + 49];
            Ac[g][w][lane] = val;
        }
    }
    __syncthreads();

    float hprev = 0.f;
    const ull* hsp = ((const ull*)h_s) + lane;

    // seed split-barrier: first bar.sync(512) needs 256 banked arrivals
    bar_arrive_1_512();

    for (int t = 0; t < L_STEPS; ++t) {
        const int buf = t & 1;

        // ---- hoisted gi table lookups (independent of h; value-identical) ----
        unsigned rc = rec_s[t];
        int vi = rc & 255, ci = (rc >> 8) & 255, mk = (rc >> 16) & 15;
        float gbr = Ts[0][w][vi] + Ts[0][w][ci] + Ac[0][w][mk];
        float gbz = Ts[1][w][vi] + Ts[1][w][ci] + Ac[1][w][mk];
        float gbn = Ts[2][w][vi] + Ts[2][w][ci] + Ac[2][w][mk];

        // ---- phase A1: relaxed tagged poll of h(t) into REGISTERS ----
        // (overlaps sibling warps' previous-step reduce/gates tail)
        ull v0, v1, v2, v3;
        {
            const unsigned tg = (unsigned)t;
            const ull* src = &g_ht[buf][0] + tid * 4;
            v0 = ld_rlx64(src + 0);
            v1 = ld_rlx64(src + 1);
            v2 = ld_rlx64(src + 2);
            v3 = ld_rlx64(src + 3);
            for (;;) {
                unsigned bad = (((unsigned)(v0 >> 32)) ^ tg)
                             | (((unsigned)(v1 >> 32)) ^ tg)
                             | (((unsigned)(v2 >> 32)) ^ tg)
                             | (((unsigned)(v3 >> 32)) ^ tg);
                if (!bad) break;
                if ((unsigned)(v0 >> 32) != tg) v0 = ld_rlx64(src + 0);
                if ((unsigned)(v1 >> 32) != tg) v1 = ld_rlx64(src + 1);
                if ((unsigned)(v2 >> 32) != tg) v2 = ld_rlx64(src + 2);
                if ((unsigned)(v3 >> 32) != tg) v3 = ld_rlx64(src + 3);
            }
        }

        // ---- phase A2: wait until all dots of step t-1 done, then stage ----
        bar_sync_1_512();
        h_s[tid * 4 + 0] = __uint_as_float((unsigned)v0);
        h_s[tid * 4 + 1] = __uint_as_float((unsigned)v1);
        h_s[tid * 4 + 2] = __uint_as_float((unsigned)v2);
        h_s[tid * 4 + 3] = __uint_as_float((unsigned)v3);
        __syncthreads();

        // ---- phase B: 4 packed dots from smem (R3 strided order) ----
        ull ar = 0ull, az = 0ull, an = 0ull, ap = 0ull;
        #pragma unroll
        for (int k = 0; k < 16; ++k) {
            ull hv = hsp[32 * k];
            ar = ffma2(wr[k], hv, ar);
            az = ffma2(wz[k], hv, az);
            an = ffma2(wn[k], hv, an);
            ap = ffma2(wp[k], hv, ap);
        }
        bar_arrive_1_512();    // h_s reads done; DON'T wait for siblings

        F2u u;
        u.u = ar; float sr = u.f.x + u.f.y;
        u.u = az; float sz = u.f.x + u.f.y;
        u.u = an; float sn = u.f.x + u.f.y;
        u.u = ap; float sp = u.f.x + u.f.y;
        #pragma unroll
        for (int m = 16; m >= 1; m >>= 1) {
            sr += __shfl_xor_sync(0xffffffffu, sr, m);
            sz += __shfl_xor_sync(0xffffffffu, sz, m);
            sn += __shfl_xor_sync(0xffffffffu, sn, m);
            sp += __shfl_xor_sync(0xffffffffu, sp, m);
        }

        // ---- phase C: gates (all lanes), tagged relaxed store ----
        float f0p = (t > 0) ? (sp + pb) : 0.f;
        float rr = fast_sig(gbr + f0p * wf0r + sr + b_r);
        float zz = fast_sig(gbz + f0p * wf0z + sz + b_z);
        float nn = fast_tanh(gbn + f0p * wf0n + rr * (sn + b_n));
        float hn = (1.f - zz) * nn + zz * hprev;
        hprev = hn;
        if (lane == 0) {
            ull pk = ((ull)(unsigned)(t + 1) << 32) | (ull)__float_as_uint(hn);
            st_rlx64(&g_ht[(t + 1) & 1][d], pk);
            if (d == 0 && t > 0) out[t - 1] = f0p;
        }
    }

    // ---- epilogue: f0(L-1) from h(L) (tag L in buf 0) ----
    if (cta == 0 && w == 0) {
        const unsigned tg = (unsigned)L_STEPS;
        ull ap = 0ull;
        #pragma unroll
        for (int k = 0; k < 16; ++k) {
            const ull* p0 = &g_ht[0][0] + 64 * k + 2 * lane;
            ull a = ld_rlx64(p0);
            while ((unsigned)(a >> 32) != tg) a = ld_rlx64(p0);
            ull b = ld_rlx64(p0 + 1);
            while ((unsigned)(b >> 32) != tg) b = ld_rlx64(p0 + 1);
            F2u hv; hv.f.x = __uint_as_float((unsigned)a);
                    hv.f.y = __uint_as_float((unsigned)b);
            ap = ffma2(wp[k], hv.u, ap);
        }
        F2u u; u.u = ap; float sp = u.f.x + u.f.y;
        #pragma unroll
        for (int m = 16; m >= 1; m >>= 1)
            sp += __shfl_xor_sync(0xffffffffu, sp, m);
        if (lane == 0) out[L_STEPS - 1] = sp + pb;
    }
}

// ---------------------------------------------------------------- launch
extern "C" void kernel_launch(void* const* d_in, const int* in_sizes, int n_in,
                              void* d_out, int out_size) {
    (void)in_sizes; (void)n_in; (void)out_size;
    const int*   vowel = (const int*)d_in[1];
    const int*   cons  = (const int*)d_in[2];
    const int*   sa    = (const int*)d_in[3];
    const int*   ea    = (const int*)d_in[4];
    const int*   sap   = (const int*)d_in[5];
    const int*   eap   = (const int*)d_in[6];
    const int*   sid   = (const int*)d_in[7];
    const float* emb   = (const float*)d_in[8];
    const float* spke  = (const float*)d_in[9];
    const float* encW  = (const float*)d_in[10];
    const float* encb  = (const float*)d_in[11];
    const float* Wih   = (const float*)d_in[12];
    const float* Whh   = (const float*)d_in[13];
    const float* bih   = (const float*)d_in[14];
    const float* bhh   = (const float*)d_in[15];
    const float* postW = (const float*)d_in[16];
    const float* postb = (const float*)d_in[17];
    float* out = (float*)d_out;

    k0_pack<<<L_STEPS / 256, 256>>>(vowel, cons, sa, ea, sap, eap);
    k1a_U<<<1024, 64>>>(encW, encb, emb, spke, sid);
    k1b_V<<<96, 256>>>(Wih);
    k3_scan<<<NCTA, 256>>>(Wih, Whh, bih, bhh, postW, postb, out);
}

// round 14
// speedup vs baseline: 1.6020x; 1.6020x over previous
#include <cuda_runtime.h>
#include <cuda_bf16.h>
#include <cstdint>

// ============================================================================
// YukarinSa f0 predictor: table-folded encoder + persistent-grid GRU scan.
//
// Round 14: R11 (best, 16.09ms) with the second __syncthreads MOVED from
// after-dots to after-store. Stores no longer wait for sibling warps'
// dots (sibling skew off the producer path); polls still strictly follow
// all local stores (stronger anti poll/store-overlap than R11). No
// arithmetic or memory-op changes — bit-exact (rel_err 1.540957e-06).
// ============================================================================

#define L_STEPS 8192
#define NCTA    128

typedef unsigned long long ull;

__device__ ull      g_ht[2][1024];    // {tag<<32 | f32bits}, one h element per word
__device__ float    g_U[51 * 1024];   // [p][i]
__device__ float    g_V[3072 * 51];   // [r][col]: 0..45=T, 46..49=A, 50=c0
__device__ unsigned g_rec[L_STEPS];

// ---------------------------------------------------------------- PTX helpers
__device__ __forceinline__ ull ffma2(ull a, ull b, ull c) {
    ull d;
    asm("fma.rn.f32x2 %0, %1, %2, %3;" : "=l"(d) : "l"(a), "l"(b), "l"(c));
    return d;
}
__device__ __forceinline__ ull ld_rlx64(const ull* p) {
    ull v;
    asm volatile("ld.relaxed.gpu.global.b64 %0, [%1];" : "=l"(v) : "l"(p));
    return v;
}
__device__ __forceinline__ void st_rlx64(ull* p, ull v) {
    asm volatile("st.relaxed.gpu.global.b64 [%0], %1;" :: "l"(p), "l"(v) : "memory");
}
__device__ __forceinline__ float fast_sig(float x) {
    float e = __expf(-x);
    return __fdividef(1.f, 1.f + e);
}
__device__ __forceinline__ float fast_tanh(float x) {
    float e = __expf(2.f * x);
    return 1.f - __fdividef(2.f, e + 1.f);
}

union F2u { ull u; float2 f; };

// ---------------------------------------------------------------- K0: pack/reset
__global__ void k0_pack(const int* __restrict__ v, const int* __restrict__ c,
                        const int* __restrict__ sa, const int* __restrict__ ea,
                        const int* __restrict__ sap, const int* __restrict__ eap) {
    int i = blockIdx.x * 256 + threadIdx.x;
    if (i < L_STEPS) {
        unsigned r = (unsigned)(v[i] + 1) | ((unsigned)(c[i] + 1) << 8)
                   | ((unsigned)(sa[i]  & 1) << 16) | ((unsigned)(ea[i]  & 1) << 17)
                   | ((unsigned)(sap[i] & 1) << 18) | ((unsigned)(eap[i] & 1) << 19);
        g_rec[i] = r;
        if (i < 1024) {
            g_ht[0][i] = 0ull;                       // tag 0, value 0.0f
            g_ht[1][i] = 0xFFFFFFFF00000000ull;      // never-matching tag
        }
    }
}

// ---------------------------------------------------------------- K1a: U fold
__global__ void k1a_U(const float* __restrict__ encW, const float* __restrict__ encb,
                      const float* __restrict__ emb,  const float* __restrict__ spkemb,
                      const int* __restrict__ sid) {
    __shared__ float ew[516];
    int i = blockIdx.x;
    int tid = threadIdx.x;
    for (int n = tid; n < 516; n += 64) ew[n] = encW[i * 516 + n];
    __syncthreads();
    if (tid < 46) {
        const float* er = emb + tid * 256;
        float s = 0.f;
        for (int e = 0; e < 256; ++e) s = fmaf(ew[e], er[e], s);
        g_U[tid * 1024 + i] = s;
    } else if (tid < 50) {
        g_U[tid * 1024 + i] = ew[256 + (tid - 46)];
    } else if (tid == 50) {
        const float* sr = spkemb + (size_t)sid[0] * 256;
        float s = encb[i];
        for (int e = 0; e < 256; ++e) s = fmaf(ew[260 + e], sr[e], s);
        g_U[50 * 1024 + i] = s;
    }
}

// ---------------------------------------------------------------- K1b: V = Wih_h @ U
__global__ void k1b_V(const float* __restrict__ Wih) {
    __shared__ float Ws[32][129];
    __shared__ float Us[56][128];
    int tid = threadIdx.x;
    int r = tid & 31, pg = tid >> 5;
    int R0 = blockIdx.x * 32;
    float acc[7] = {0.f, 0.f, 0.f, 0.f, 0.f, 0.f, 0.f};
    for (int k0 = 0; k0 < 1024; k0 += 128) {
        for (int n = tid; n < 32 * 128; n += 256) {
            int rr = n >> 7, cc = n & 127;
            Ws[rr][cc] = Wih[(size_t)(R0 + rr) * 1025 + k0 + cc];
        }
        for (int n = tid; n < 56 * 128; n += 256) {
            int pp = n >> 7, cc = n & 127;
            Us[pp][cc] = (pp < 51) ? g_U[pp * 1024 + k0 + cc] : 0.f;
        }
        __syncthreads();
        #pragma unroll 4
        for (int kk = 0; kk < 128; ++kk) {
            float wv = Ws[r][kk];
            #pragma unroll
            for (int j = 0; j < 7; ++j)
                acc[j] = fmaf(wv, Us[pg + 8 * j][kk], acc[j]);
        }
        __syncthreads();
    }
    #pragma unroll
    for (int j = 0; j < 7; ++j) {
        int p = pg + 8 * j;
        if (p < 51) g_V[(size_t)(R0 + r) * 51 + p] = acc[j];
    }
}

// ---------------------------------------------------------------- K3: persistent scan
__global__ void __launch_bounds__(256, 1)
k3_scan(const float* __restrict__ Wih, const float* __restrict__ Whh,
        const float* __restrict__ bih, const float* __restrict__ bhh,
        const float* __restrict__ postW, const float* __restrict__ postb,
        float* __restrict__ out) {
    __shared__ unsigned rec_s[L_STEPS];
    __shared__ __align__(16) float h_s[1024];
    __shared__ float Ts[3][8][46];
    __shared__ float Ac[3][8][16];

    const int tid  = threadIdx.x;
    const int w    = tid >> 5;
    const int lane = tid & 31;
    const int cta  = blockIdx.x;
    const int d    = cta * 8 + w;          // owned h-dim

    // --- register-resident weight pairs, R3 strided layout:
    //     wr[k] at ull index lane+32k covers h floats 2*lane+64k, +1
    ull wr[16], wz[16], wn[16], wp[16];
    {
        const ull* pr = (const ull*)(Whh + (size_t)d          * 1024) + lane;
        const ull* pz = (const ull*)(Whh + (size_t)(1024 + d) * 1024) + lane;
        const ull* pn = (const ull*)(Whh + (size_t)(2048 + d) * 1024) + lane;
        const ull* pp = (const ull*)(postW) + lane;
        #pragma unroll
        for (int k = 0; k < 16; ++k) {
            wr[k] = pr[32 * k]; wz[k] = pz[32 * k];
            wn[k] = pn[32 * k]; wp[k] = pp[32 * k];
        }
    }
    const float b_r  = bhh[d], b_z = bhh[1024 + d], b_n = bhh[2048 + d];
    const float wf0r = Wih[(size_t)d          * 1025 + 1024];
    const float wf0z = Wih[(size_t)(1024 + d) * 1025 + 1024];
    const float wf0n = Wih[(size_t)(2048 + d) * 1025 + 1024];
    const float pb   = postb[0];

    // --- shared tables ---
    for (int n = tid; n < L_STEPS; n += 256) rec_s[n] = g_rec[n];
    for (int n = tid; n < 3 * 8 * 46; n += 256) {
        int g = n / 368, rm = n - g * 368, w2 = rm / 46, p = rm - w2 * 46;
        Ts[g][w2][p] = g_V[(size_t)(cta * 8 + w2 + g * 1024) * 51 + p];
    }
    #pragma unroll
    for (int g = 0; g < 3; ++g) {
        int r = d + g * 1024;
        if (lane < 16) {
            float val = g_V[(size_t)r * 51 + 50] + bih[r];
            if (lane & 1) val += g_V[(size_t)r * 51 + 46];
            if (lane & 2) val += g_V[(size_t)r * 51 + 47];
            if (lane & 4) val += g_V[(size_t)r * 51 + 48];
            if (lane & 8) val += g_V[(size_t)r * 51 + 49];
            Ac[g][w][lane] = val;
        }
    }
    __syncthreads();

    float hprev = 0.f;
    const ull* hsp = ((const ull*)h_s) + lane;

    for (int t = 0; t < L_STEPS; ++t) {
        const int buf = t & 1;

        // ---- hoisted gi table lookups (independent of h; value-identical) ----
        unsigned rc = rec_s[t];
        int vi = rc & 255, ci = (rc >> 8) & 255, mk = (rc >> 16) & 15;
        float gbr = Ts[0][w][vi] + Ts[0][w][ci] + Ac[0][w][mk];
        float gbz = Ts[1][w][vi] + Ts[1][w][ci] + Ac[1][w][mk];
        float gbn = Ts[2][w][vi] + Ts[2][w][ci] + Ac[2][w][mk];

        // ---- phase A: relaxed tagged poll of h(t), stage to smem ----
        // (h_s overwrite is safe: previous step's BAR2 [after store] proves
        //  every sibling warp finished its dots)
        {
            const unsigned tg = (unsigned)t;
            const ull* src = &g_ht[buf][0] + tid * 4;
            ull v0 = ld_rlx64(src + 0);
            ull v1 = ld_rlx64(src + 1);
            ull v2 = ld_rlx64(src + 2);
            ull v3 = ld_rlx64(src + 3);
            for (;;) {
                unsigned bad = (((unsigned)(v0 >> 32)) ^ tg)
                             | (((unsigned)(v1 >> 32)) ^ tg)
                             | (((unsigned)(v2 >> 32)) ^ tg)
                             | (((unsigned)(v3 >> 32)) ^ tg);
                if (!bad) break;
                if ((unsigned)(v0 >> 32) != tg) v0 = ld_rlx64(src + 0);
                if ((unsigned)(v1 >> 32) != tg) v1 = ld_rlx64(src + 1);
                if ((unsigned)(v2 >> 32) != tg) v2 = ld_rlx64(src + 2);
                if ((unsigned)(v3 >> 32) != tg) v3 = ld_rlx64(src + 3);
            }
            h_s[tid * 4 + 0] = __uint_as_float((unsigned)v0);
            h_s[tid * 4 + 1] = __uint_as_float((unsigned)v1);
            h_s[tid * 4 + 2] = __uint_as_float((unsigned)v2);
            h_s[tid * 4 + 3] = __uint_as_float((unsigned)v3);
        }
        __syncthreads();                       // BAR1: stage -> dots

        // ---- phase B: 4 packed dots from smem (R3 strided order) ----
        ull ar = 0ull, az = 0ull, an = 0ull, ap = 0ull;
        #pragma unroll
        for (int k = 0; k < 16; ++k) {
            ull hv = hsp[32 * k];
            ar = ffma2(wr[k], hv, ar);
            az = ffma2(wz[k], hv, az);
            an = ffma2(wn[k], hv, an);
            ap = ffma2(wp[k], hv, ap);
        }

        // ---- reduce + gates + store proceed WITHOUT waiting for siblings ----
        F2u u;
        u.u = ar; float sr = u.f.x + u.f.y;
        u.u = az; float sz = u.f.x + u.f.y;
        u.u = an; float sn = u.f.x + u.f.y;
        u.u = ap; float sp = u.f.x + u.f.y;
        #pragma unroll
        for (int m = 16; m >= 1; m >>= 1) {
            sr += __shfl_xor_sync(0xffffffffu, sr, m);
            sz += __shfl_xor_sync(0xffffffffu, sz, m);
            sn += __shfl_xor_sync(0xffffffffu, sn, m);
            sp += __shfl_xor_sync(0xffffffffu, sp, m);
        }

        float f0p = (t > 0) ? (sp + pb) : 0.f;
        float rr = fast_sig(gbr + f0p * wf0r + sr + b_r);
        float zz = fast_sig(gbz + f0p * wf0z + sz + b_z);
        float nn = fast_tanh(gbn + f0p * wf0n + rr * (sn + b_n));
        float hn = (1.f - zz) * nn + zz * hprev;
        hprev = hn;
        if (lane == 0) {
            ull pk = ((ull)(unsigned)(t + 1) << 32) | (ull)__float_as_uint(hn);
            st_rlx64(&g_ht[(t + 1) & 1][d], pk);
            if (d == 0 && t > 0) out[t - 1] = f0p;
        }

        __syncthreads();                       // BAR2: all stores issued ->
                                               // next poll can't overlap them
    }

    // ---- epilogue: f0(L-1) from h(L) (tag L in buf 0) ----
    if (cta == 0 && w == 0) {
        const unsigned tg = (unsigned)L_STEPS;
        ull ap = 0ull;
        #pragma unroll
        for (int k = 0; k < 16; ++k) {
            const ull* p0 = &g_ht[0][0] + 64 * k + 2 * lane;
            ull a = ld_rlx64(p0);
            while ((unsigned)(a >> 32) != tg) a = ld_rlx64(p0);
            ull b = ld_rlx64(p0 + 1);
            while ((unsigned)(b >> 32) != tg) b = ld_rlx64(p0 + 1);
            F2u hv; hv.f.x = __uint_as_float((unsigned)a);
                    hv.f.y = __uint_as_float((unsigned)b);
            ap = ffma2(wp[k], hv.u, ap);
        }
        F2u u; u.u = ap; float sp = u.f.x + u.f.y;
        #pragma unroll
        for (int m = 16; m >= 1; m >>= 1)
            sp += __shfl_xor_sync(0xffffffffu, sp, m);
        if (lane == 0) out[L_STEPS - 1] = sp + pb;
    }
}

// ---------------------------------------------------------------- launch
extern "C" void kernel_launch(void* const* d_in, const int* in_sizes, int n_in,
                              void* d_out, int out_size) {
    (void)in_sizes; (void)n_in; (void)out_size;
    const int*   vowel = (const int*)d_in[1];
    const int*   cons  = (const int*)d_in[2];
    const int*   sa    = (const int*)d_in[3];
    const int*   ea    = (const int*)d_in[4];
    const int*   sap   = (const int*)d_in[5];
    const int*   eap   = (const int*)d_in[6];
    const int*   sid   = (const int*)d_in[7];
    const float* emb   = (const float*)d_in[8];
    const float* spke  = (const float*)d_in[9];
    const float* encW  = (const float*)d_in[10];
    const float* encb  = (const float*)d_in[11];
    const float* Wih   = (const float*)d_in[12];
    const float* Whh   = (const float*)d_in[13];
    const float* bih   = (const float*)d_in[14];
    const float* bhh   = (const float*)d_in[15];
    const float* postW = (const float*)d_in[16];
    const float* postb = (const float*)d_in[17];
    float* out = (float*)d_out;

    k0_pack<<<L_STEPS / 256, 256>>>(vowel, cons, sa, ea, sap, eap);
    k1a_U<<<1024, 64>>>(encW, encb, emb, spke, sid);
    k1b_V<<<96, 256>>>(Wih);
    k3_scan<<<NCTA, 256>>>(Wih, Whh, bih, bhh, postW, postb, out);
}

// round 15
// speedup vs baseline: 2.7148x; 1.6946x over previous
#include <cuda_runtime.h>
#include <cuda_bf16.h>
#include <cstdint>

// ============================================================================
// YukarinSa f0 predictor: table-folded encoder + persistent-grid GRU scan.
//
// Round 15: R11 (best, 16.09ms) with the tagged h buffer PADDED to 32B
// stride (word i at ull index 4i). Spreads the 8KB of tagged words over
// 256 L2 lines instead of 64, cutting per-slice response queueing in the
// poll round ~4x. Phase order, store/load counts, and arithmetic are
// IDENTICAL to R11 (bit-exact, rel_err 1.540957e-06).
// ============================================================================

#define L_STEPS 8192
#define NCTA    128
#define HSTRIDE 4            // ull stride between tagged words (32B)

typedef unsigned long long ull;

__device__ ull      g_ht[2][1024 * HSTRIDE];  // {tag<<32 | f32bits} at index 4*i
__device__ float    g_U[51 * 1024];   // [p][i]
__device__ float    g_V[3072 * 51];   // [r][col]: 0..45=T, 46..49=A, 50=c0
__device__ unsigned g_rec[L_STEPS];

// ---------------------------------------------------------------- PTX helpers
__device__ __forceinline__ ull ffma2(ull a, ull b, ull c) {
    ull d;
    asm("fma.rn.f32x2 %0, %1, %2, %3;" : "=l"(d) : "l"(a), "l"(b), "l"(c));
    return d;
}
__device__ __forceinline__ ull ld_rlx64(const ull* p) {
    ull v;
    asm volatile("ld.relaxed.gpu.global.b64 %0, [%1];" : "=l"(v) : "l"(p));
    return v;
}
__device__ __forceinline__ void st_rlx64(ull* p, ull v) {
    asm volatile("st.relaxed.gpu.global.b64 [%0], %1;" :: "l"(p), "l"(v) : "memory");
}
__device__ __forceinline__ float fast_sig(float x) {
    float e = __expf(-x);
    return __fdividef(1.f, 1.f + e);
}
__device__ __forceinline__ float fast_tanh(float x) {
    float e = __expf(2.f * x);
    return 1.f - __fdividef(2.f, e + 1.f);
}

union F2u { ull u; float2 f; };

// ---------------------------------------------------------------- K0: pack/reset
__global__ void k0_pack(const int* __restrict__ v, const int* __restrict__ c,
                        const int* __restrict__ sa, const int* __restrict__ ea,
                        const int* __restrict__ sap, const int* __restrict__ eap) {
    int i = blockIdx.x * 256 + threadIdx.x;
    if (i < L_STEPS) {
        unsigned r = (unsigned)(v[i] + 1) | ((unsigned)(c[i] + 1) << 8)
                   | ((unsigned)(sa[i]  & 1) << 16) | ((unsigned)(ea[i]  & 1) << 17)
                   | ((unsigned)(sap[i] & 1) << 18) | ((unsigned)(eap[i] & 1) << 19);
        g_rec[i] = r;
        if (i < 1024 * HSTRIDE) {
            g_ht[0][i] = 0ull;                       // tag 0, value 0.0f
            g_ht[1][i] = 0xFFFFFFFF00000000ull;      // never-matching tag
        }
    }
}

// ---------------------------------------------------------------- K1a: U fold
__global__ void k1a_U(const float* __restrict__ encW, const float* __restrict__ encb,
                      const float* __restrict__ emb,  const float* __restrict__ spkemb,
                      const int* __restrict__ sid) {
    __shared__ float ew[516];
    int i = blockIdx.x;
    int tid = threadIdx.x;
    for (int n = tid; n < 516; n += 64) ew[n] = encW[i * 516 + n];
    __syncthreads();
    if (tid < 46) {
        const float* er = emb + tid * 256;
        float s = 0.f;
        for (int e = 0; e < 256; ++e) s = fmaf(ew[e], er[e], s);
        g_U[tid * 1024 + i] = s;
    } else if (tid < 50) {
        g_U[tid * 1024 + i] = ew[256 + (tid - 46)];
    } else if (tid == 50) {
        const float* sr = spkemb + (size_t)sid[0] * 256;
        float s = encb[i];
        for (int e = 0; e < 256; ++e) s = fmaf(ew[260 + e], sr[e], s);
        g_U[50 * 1024 + i] = s;
    }
}

// ---------------------------------------------------------------- K1b: V = Wih_h @ U
__global__ void k1b_V(const float* __restrict__ Wih) {
    __shared__ float Ws[32][129];
    __shared__ float Us[56][128];
    int tid = threadIdx.x;
    int r = tid & 31, pg = tid >> 5;
    int R0 = blockIdx.x * 32;
    float acc[7] = {0.f, 0.f, 0.f, 0.f, 0.f, 0.f, 0.f};
    for (int k0 = 0; k0 < 1024; k0 += 128) {
        for (int n = tid; n < 32 * 128; n += 256) {
            int rr = n >> 7, cc = n & 127;
            Ws[rr][cc] = Wih[(size_t)(R0 + rr) * 1025 + k0 + cc];
        }
        for (int n = tid; n < 56 * 128; n += 256) {
            int pp = n >> 7, cc = n & 127;
            Us[pp][cc] = (pp < 51) ? g_U[pp * 1024 + k0 + cc] : 0.f;
        }
        __syncthreads();
        #pragma unroll 4
        for (int kk = 0; kk < 128; ++kk) {
            float wv = Ws[r][kk];
            #pragma unroll
            for (int j = 0; j < 7; ++j)
                acc[j] = fmaf(wv, Us[pg + 8 * j][kk], acc[j]);
        }
        __syncthreads();
    }
    #pragma unroll
    for (int j = 0; j < 7; ++j) {
        int p = pg + 8 * j;
        if (p < 51) g_V[(size_t)(R0 + r) * 51 + p] = acc[j];
    }
}

// ---------------------------------------------------------------- K3: persistent scan
__global__ void __launch_bounds__(256, 1)
k3_scan(const float* __restrict__ Wih, const float* __restrict__ Whh,
        const float* __restrict__ bih, const float* __restrict__ bhh,
        const float* __restrict__ postW, const float* __restrict__ postb,
        float* __restrict__ out) {
    __shared__ unsigned rec_s[L_STEPS];
    __shared__ __align__(16) float h_s[1024];
    __shared__ float Ts[3][8][46];
    __shared__ float Ac[3][8][16];

    const int tid  = threadIdx.x;
    const int w    = tid >> 5;
    const int lane = tid & 31;
    const int cta  = blockIdx.x;
    const int d    = cta * 8 + w;          // owned h-dim

    // --- register-resident weight pairs, R3 strided layout:
    //     wr[k] at ull index lane+32k covers h floats 2*lane+64k, +1
    ull wr[16], wz[16], wn[16], wp[16];
    {
        const ull* pr = (const ull*)(Whh + (size_t)d          * 1024) + lane;
        const ull* pz = (const ull*)(Whh + (size_t)(1024 + d) * 1024) + lane;
        const ull* pn = (const ull*)(Whh + (size_t)(2048 + d) * 1024) + lane;
        const ull* pp = (const ull*)(postW) + lane;
        #pragma unroll
        for (int k = 0; k < 16; ++k) {
            wr[k] = pr[32 * k]; wz[k] = pz[32 * k];
            wn[k] = pn[32 * k]; wp[k] = pp[32 * k];
        }
    }
    const float b_r  = bhh[d], b_z = bhh[1024 + d], b_n = bhh[2048 + d];
    const float wf0r = Wih[(size_t)d          * 1025 + 1024];
    const float wf0z = Wih[(size_t)(1024 + d) * 1025 + 1024];
    const float wf0n = Wih[(size_t)(2048 + d) * 1025 + 1024];
    const float pb   = postb[0];

    // --- shared tables ---
    for (int n = tid; n < L_STEPS; n += 256) rec_s[n] = g_rec[n];
    for (int n = tid; n < 3 * 8 * 46; n += 256) {
        int g = n / 368, rm = n - g * 368, w2 = rm / 46, p = rm - w2 * 46;
        Ts[g][w2][p] = g_V[(size_t)(cta * 8 + w2 + g * 1024) * 51 + p];
    }
    #pragma unroll
    for (int g = 0; g < 3; ++g) {
        int r = d + g * 1024;
        if (lane < 16) {
            float val = g_V[(size_t)r * 51 + 50] + bih[r];
            if (lane & 1) val += g_V[(size_t)r * 51 + 46];
            if (lane & 2) val += g_V[(size_t)r * 51 + 47];
            if (lane & 4) val += g_V[(size_t)r * 51 + 48];
            if (lane & 8) val += g_V[(size_t)r * 51 + 49];
            Ac[g][w][lane] = val;
        }
    }
    __syncthreads();

    float hprev = 0.f;
    const ull* hsp = ((const ull*)h_s) + lane;

    for (int t = 0; t < L_STEPS; ++t) {
        const int buf = t & 1;

        // ---- hoisted gi table lookups (independent of h; value-identical) ----
        unsigned rc = rec_s[t];
        int vi = rc & 255, ci = (rc >> 8) & 255, mk = (rc >> 16) & 15;
        float gbr = Ts[0][w][vi] + Ts[0][w][ci] + Ac[0][w][mk];
        float gbz = Ts[1][w][vi] + Ts[1][w][ci] + Ac[1][w][mk];
        float gbn = Ts[2][w][vi] + Ts[2][w][ci] + Ac[2][w][mk];

        // ---- phase A: relaxed tagged poll of h(t), stage to smem ----
        // word i lives at ull index i*HSTRIDE (32B stride -> 256 L2 lines)
        {
            const unsigned tg = (unsigned)t;
            const ull* src = &g_ht[buf][0] + (size_t)tid * 4 * HSTRIDE;
            ull v0 = ld_rlx64(src + 0 * HSTRIDE);
            ull v1 = ld_rlx64(src + 1 * HSTRIDE);
            ull v2 = ld_rlx64(src + 2 * HSTRIDE);
            ull v3 = ld_rlx64(src + 3 * HSTRIDE);
            for (;;) {
                unsigned bad = (((unsigned)(v0 >> 32)) ^ tg)
                             | (((unsigned)(v1 >> 32)) ^ tg)
                             | (((unsigned)(v2 >> 32)) ^ tg)
                             | (((unsigned)(v3 >> 32)) ^ tg);
                if (!bad) break;
                if ((unsigned)(v0 >> 32) != tg) v0 = ld_rlx64(src + 0 * HSTRIDE);
                if ((unsigned)(v1 >> 32) != tg) v1 = ld_rlx64(src + 1 * HSTRIDE);
                if ((unsigned)(v2 >> 32) != tg) v2 = ld_rlx64(src + 2 * HSTRIDE);
                if ((unsigned)(v3 >> 32) != tg) v3 = ld_rlx64(src + 3 * HSTRIDE);
            }
            h_s[tid * 4 + 0] = __uint_as_float((unsigned)v0);
            h_s[tid * 4 + 1] = __uint_as_float((unsigned)v1);
            h_s[tid * 4 + 2] = __uint_as_float((unsigned)v2);
            h_s[tid * 4 + 3] = __uint_as_float((unsigned)v3);
        }
        __syncthreads();

        // ---- phase B: 4 packed dots from smem (R3 strided order) ----
        ull ar = 0ull, az = 0ull, an = 0ull, ap = 0ull;
        #pragma unroll
        for (int k = 0; k < 16; ++k) {
            ull hv = hsp[32 * k];
            ar = ffma2(wr[k], hv, ar);
            az = ffma2(wz[k], hv, az);
            an = ffma2(wn[k], hv, an);
            ap = ffma2(wp[k], hv, ap);
        }
        __syncthreads();   // keeps all 8 warps' stores in one tight burst

        F2u u;
        u.u = ar; float sr = u.f.x + u.f.y;
        u.u = az; float sz = u.f.x + u.f.y;
        u.u = an; float sn = u.f.x + u.f.y;
        u.u = ap; float sp = u.f.x + u.f.y;
        #pragma unroll
        for (int m = 16; m >= 1; m >>= 1) {
            sr += __shfl_xor_sync(0xffffffffu, sr, m);
            sz += __shfl_xor_sync(0xffffffffu, sz, m);
            sn += __shfl_xor_sync(0xffffffffu, sn, m);
            sp += __shfl_xor_sync(0xffffffffu, sp, m);
        }

        // ---- phase C: gates (all lanes), tagged relaxed store ----
        float f0p = (t > 0) ? (sp + pb) : 0.f;
        float rr = fast_sig(gbr + f0p * wf0r + sr + b_r);
        float zz = fast_sig(gbz + f0p * wf0z + sz + b_z);
        float nn = fast_tanh(gbn + f0p * wf0n + rr * (sn + b_n));
        float hn = (1.f - zz) * nn + zz * hprev;
        hprev = hn;
        if (lane == 0) {
            ull pk = ((ull)(unsigned)(t + 1) << 32) | (ull)__float_as_uint(hn);
            st_rlx64(&g_ht[(t + 1) & 1][(size_t)d * HSTRIDE], pk);
            if (d == 0 && t > 0) out[t - 1] = f0p;
        }
    }

    // ---- epilogue: f0(L-1) from h(L) (tag L in buf 0) ----
    if (cta == 0 && w == 0) {
        const unsigned tg = (unsigned)L_STEPS;
        ull ap = 0ull;
        #pragma unroll
        for (int k = 0; k < 16; ++k) {
            const ull* p0 = &g_ht[0][0] + (size_t)(64 * k + 2 * lane) * HSTRIDE;
            ull a = ld_rlx64(p0);
            while ((unsigned)(a >> 32) != tg) a = ld_rlx64(p0);
            ull b = ld_rlx64(p0 + HSTRIDE);
            while ((unsigned)(b >> 32) != tg) b = ld_rlx64(p0 + HSTRIDE);
            F2u hv; hv.f.x = __uint_as_float((unsigned)a);
                    hv.f.y = __uint_as_float((unsigned)b);
            ap = ffma2(wp[k], hv.u, ap);
        }
        F2u u; u.u = ap; float sp = u.f.x + u.f.y;
        #pragma unroll
        for (int m = 16; m >= 1; m >>= 1)
            sp += __shfl_xor_sync(0xffffffffu, sp, m);
        if (lane == 0) out[L_STEPS - 1] = sp + pb;
    }
}

// ---------------------------------------------------------------- launch
extern "C" void kernel_launch(void* const* d_in, const int* in_sizes, int n_in,
                              void* d_out, int out_size) {
    (void)in_sizes; (void)n_in; (void)out_size;
    const int*   vowel = (const int*)d_in[1];
    const int*   cons  = (const int*)d_in[2];
    const int*   sa    = (const int*)d_in[3];
    const int*   ea    = (const int*)d_in[4];
    const int*   sap   = (const int*)d_in[5];
    const int*   eap   = (const int*)d_in[6];
    const int*   sid   = (const int*)d_in[7];
    const float* emb   = (const float*)d_in[8];
    const float* spke  = (const float*)d_in[9];
    const float* encW  = (const float*)d_in[10];
    const float* encb  = (const float*)d_in[11];
    const float* Wih   = (const float*)d_in[12];
    const float* Whh   = (const float*)d_in[13];
    const float* bih   = (const float*)d_in[14];
    const float* bhh   = (const float*)d_in[15];
    const float* postW = (const float*)d_in[16];
    const float* postb = (const float*)d_in[17];
    float* out = (float*)d_out;

    k0_pack<<<L_STEPS / 256, 256>>>(vowel, cons, sa, ea, sap, eap);
    k1a_U<<<1024, 64>>>(encW, encb, emb, spke, sid);
    k1b_V<<<96, 256>>>(Wih);
    k3_scan<<<NCTA, 256>>>(Wih, Whh, bih, bhh, postW, postb, out);
}

// round 16
// speedup vs baseline: 3.3952x; 1.2506x over previous
#include <cuda_runtime.h>
#include <cuda_bf16.h>
#include <cstdint>

// ============================================================================
// YukarinSa f0 predictor: table-folded encoder + persistent-grid GRU scan.
//
// Round 16: R11 (best, 16.09ms) with the poll ADDRESS PERMUTATION fixed
// for coalescing: thread tid polls words {tid, tid+256, tid+512, tid+768}
// (warp-contiguous 256B requests, fully-used sectors) instead of
// {4tid..4tid+3} (32 scattered sectors per warp-load, 4x L2 service
// amplification). smem contents, instruction counts, phase order, and all
// arithmetic are IDENTICAL to R11 (bit-exact, rel_err 1.540957e-06).
// ============================================================================

#define L_STEPS 8192
#define NCTA    128

typedef unsigned long long ull;

__device__ ull      g_ht[2][1024];    // {tag<<32 | f32bits}, one h element per word
__device__ float    g_U[51 * 1024];   // [p][i]
__device__ float    g_V[3072 * 51];   // [r][col]: 0..45=T, 46..49=A, 50=c0
__device__ unsigned g_rec[L_STEPS];

// ---------------------------------------------------------------- PTX helpers
__device__ __forceinline__ ull ffma2(ull a, ull b, ull c) {
    ull d;
    asm("fma.rn.f32x2 %0, %1, %2, %3;" : "=l"(d) : "l"(a), "l"(b), "l"(c));
    return d;
}
__device__ __forceinline__ ull ld_rlx64(const ull* p) {
    ull v;
    asm volatile("ld.relaxed.gpu.global.b64 %0, [%1];" : "=l"(v) : "l"(p));
    return v;
}
__device__ __forceinline__ void st_rlx64(ull* p, ull v) {
    asm volatile("st.relaxed.gpu.global.b64 [%0], %1;" :: "l"(p), "l"(v) : "memory");
}
__device__ __forceinline__ float fast_sig(float x) {
    float e = __expf(-x);
    return __fdividef(1.f, 1.f + e);
}
__device__ __forceinline__ float fast_tanh(float x) {
    float e = __expf(2.f * x);
    return 1.f - __fdividef(2.f, e + 1.f);
}

union F2u { ull u; float2 f; };

// ---------------------------------------------------------------- K0: pack/reset
__global__ void k0_pack(const int* __restrict__ v, const int* __restrict__ c,
                        const int* __restrict__ sa, const int* __restrict__ ea,
                        const int* __restrict__ sap, const int* __restrict__ eap) {
    int i = blockIdx.x * 256 + threadIdx.x;
    if (i < L_STEPS) {
        unsigned r = (unsigned)(v[i] + 1) | ((unsigned)(c[i] + 1) << 8)
                   | ((unsigned)(sa[i]  & 1) << 16) | ((unsigned)(ea[i]  & 1) << 17)
                   | ((unsigned)(sap[i] & 1) << 18) | ((unsigned)(eap[i] & 1) << 19);
        g_rec[i] = r;
        if (i < 1024) {
            g_ht[0][i] = 0ull;                       // tag 0, value 0.0f
            g_ht[1][i] = 0xFFFFFFFF00000000ull;      // never-matching tag
        }
    }
}

// ---------------------------------------------------------------- K1a: U fold
__global__ void k1a_U(const float* __restrict__ encW, const float* __restrict__ encb,
                      const float* __restrict__ emb,  const float* __restrict__ spkemb,
                      const int* __restrict__ sid) {
    __shared__ float ew[516];
    int i = blockIdx.x;
    int tid = threadIdx.x;
    for (int n = tid; n < 516; n += 64) ew[n] = encW[i * 516 + n];
    __syncthreads();
    if (tid < 46) {
        const float* er = emb + tid * 256;
        float s = 0.f;
        for (int e = 0; e < 256; ++e) s = fmaf(ew[e], er[e], s);
        g_U[tid * 1024 + i] = s;
    } else if (tid < 50) {
        g_U[tid * 1024 + i] = ew[256 + (tid - 46)];
    } else if (tid == 50) {
        const float* sr = spkemb + (size_t)sid[0] * 256;
        float s = encb[i];
        for (int e = 0; e < 256; ++e) s = fmaf(ew[260 + e], sr[e], s);
        g_U[50 * 1024 + i] = s;
    }
}

// ---------------------------------------------------------------- K1b: V = Wih_h @ U
__global__ void k1b_V(const float* __restrict__ Wih) {
    __shared__ float Ws[32][129];
    __shared__ float Us[56][128];
    int tid = threadIdx.x;
    int r = tid & 31, pg = tid >> 5;
    int R0 = blockIdx.x * 32;
    float acc[7] = {0.f, 0.f, 0.f, 0.f, 0.f, 0.f, 0.f};
    for (int k0 = 0; k0 < 1024; k0 += 128) {
        for (int n = tid; n < 32 * 128; n += 256) {
            int rr = n >> 7, cc = n & 127;
            Ws[rr][cc] = Wih[(size_t)(R0 + rr) * 1025 + k0 + cc];
        }
        for (int n = tid; n < 56 * 128; n += 256) {
            int pp = n >> 7, cc = n & 127;
            Us[pp][cc] = (pp < 51) ? g_U[pp * 1024 + k0 + cc] : 0.f;
        }
        __syncthreads();
        #pragma unroll 4
        for (int kk = 0; kk < 128; ++kk) {
            float wv = Ws[r][kk];
            #pragma unroll
            for (int j = 0; j < 7; ++j)
                acc[j] = fmaf(wv, Us[pg + 8 * j][kk], acc[j]);
        }
        __syncthreads();
    }
    #pragma unroll
    for (int j = 0; j < 7; ++j) {
        int p = pg + 8 * j;
        if (p < 51) g_V[(size_t)(R0 + r) * 51 + p] = acc[j];
    }
}

// ---------------------------------------------------------------- K3: persistent scan
__global__ void __launch_bounds__(256, 1)
k3_scan(const float* __restrict__ Wih, const float* __restrict__ Whh,
        const float* __restrict__ bih, const float* __restrict__ bhh,
        const float* __restrict__ postW, const float* __restrict__ postb,
        float* __restrict__ out) {
    __shared__ unsigned rec_s[L_STEPS];
    __shared__ __align__(16) float h_s[1024];
    __shared__ float Ts[3][8][46];
    __shared__ float Ac[3][8][16];

    const int tid  = threadIdx.x;
    const int w    = tid >> 5;
    const int lane = tid & 31;
    const int cta  = blockIdx.x;
    const int d    = cta * 8 + w;          // owned h-dim

    // --- register-resident weight pairs, R3 strided layout:
    //     wr[k] at ull index lane+32k covers h floats 2*lane+64k, +1
    ull wr[16], wz[16], wn[16], wp[16];
    {
        const ull* pr = (const ull*)(Whh + (size_t)d          * 1024) + lane;
        const ull* pz = (const ull*)(Whh + (size_t)(1024 + d) * 1024) + lane;
        const ull* pn = (const ull*)(Whh + (size_t)(2048 + d) * 1024) + lane;
        const ull* pp = (const ull*)(postW) + lane;
        #pragma unroll
        for (int k = 0; k < 16; ++k) {
            wr[k] = pr[32 * k]; wz[k] = pz[32 * k];
            wn[k] = pn[32 * k]; wp[k] = pp[32 * k];
        }
    }
    const float b_r  = bhh[d], b_z = bhh[1024 + d], b_n = bhh[2048 + d];
    const float wf0r = Wih[(size_t)d          * 1025 + 1024];
    const float wf0z = Wih[(size_t)(1024 + d) * 1025 + 1024];
    const float wf0n = Wih[(size_t)(2048 + d) * 1025 + 1024];
    const float pb   = postb[0];

    // --- shared tables ---
    for (int n = tid; n < L_STEPS; n += 256) rec_s[n] = g_rec[n];
    for (int n = tid; n < 3 * 8 * 46; n += 256) {
        int g = n / 368, rm = n - g * 368, w2 = rm / 46, p = rm - w2 * 46;
        Ts[g][w2][p] = g_V[(size_t)(cta * 8 + w2 + g * 1024) * 51 + p];
    }
    #pragma unroll
    for (int g = 0; g < 3; ++g) {
        int r = d + g * 1024;
        if (lane < 16) {
            float val = g_V[(size_t)r * 51 + 50] + bih[r];
            if (lane & 1) val += g_V[(size_t)r * 51 + 46];
            if (lane & 2) val += g_V[(size_t)r * 51 + 47];
            if (lane & 4) val += g_V[(size_t)r * 51 + 48];
            if (lane & 8) val += g_V[(size_t)r * 51 + 49];
            Ac[g][w][lane] = val;
        }
    }
    __syncthreads();

    float hprev = 0.f;
    const ull* hsp = ((const ull*)h_s) + lane;

    for (int t = 0; t < L_STEPS; ++t) {
        const int buf = t & 1;

        // ---- hoisted gi table lookups (independent of h; value-identical) ----
        unsigned rc = rec_s[t];
        int vi = rc & 255, ci = (rc >> 8) & 255, mk = (rc >> 16) & 15;
        float gbr = Ts[0][w][vi] + Ts[0][w][ci] + Ac[0][w][mk];
        float gbz = Ts[1][w][vi] + Ts[1][w][ci] + Ac[1][w][mk];
        float gbn = Ts[2][w][vi] + Ts[2][w][ci] + Ac[2][w][mk];

        // ---- phase A: relaxed tagged poll of h(t), stage to smem ----
        // COALESCED permutation: thread tid owns words tid+256k (warp-load =
        // 32 consecutive words = 256B contiguous, fully-used sectors)
        {
            const unsigned tg = (unsigned)t;
            const ull* src = &g_ht[buf][0] + tid;
            ull v0 = ld_rlx64(src + 0);
            ull v1 = ld_rlx64(src + 256);
            ull v2 = ld_rlx64(src + 512);
            ull v3 = ld_rlx64(src + 768);
            for (;;) {
                unsigned bad = (((unsigned)(v0 >> 32)) ^ tg)
                             | (((unsigned)(v1 >> 32)) ^ tg)
                             | (((unsigned)(v2 >> 32)) ^ tg)
                             | (((unsigned)(v3 >> 32)) ^ tg);
                if (!bad) break;
                if ((unsigned)(v0 >> 32) != tg) v0 = ld_rlx64(src + 0);
                if ((unsigned)(v1 >> 32) != tg) v1 = ld_rlx64(src + 256);
                if ((unsigned)(v2 >> 32) != tg) v2 = ld_rlx64(src + 512);
                if ((unsigned)(v3 >> 32) != tg) v3 = ld_rlx64(src + 768);
            }
            h_s[tid +   0] = __uint_as_float((unsigned)v0);
            h_s[tid + 256] = __uint_as_float((unsigned)v1);
            h_s[tid + 512] = __uint_as_float((unsigned)v2);
            h_s[tid + 768] = __uint_as_float((unsigned)v3);
        }
        __syncthreads();

        // ---- phase B: 4 packed dots from smem (R3 strided order) ----
        ull ar = 0ull, az = 0ull, an = 0ull, ap = 0ull;
        #pragma unroll
        for (int k = 0; k < 16; ++k) {
            ull hv = hsp[32 * k];
            ar = ffma2(wr[k], hv, ar);
            az = ffma2(wz[k], hv, az);
            an = ffma2(wn[k], hv, an);
            ap = ffma2(wp[k], hv, ap);
        }
        __syncthreads();   // keeps all 8 warps' stores in one tight burst

        F2u u;
        u.u = ar; float sr = u.f.x + u.f.y;
        u.u = az; float sz = u.f.x + u.f.y;
        u.u = an; float sn = u.f.x + u.f.y;
        u.u = ap; float sp = u.f.x + u.f.y;
        #pragma unroll
        for (int m = 16; m >= 1; m >>= 1) {
            sr += __shfl_xor_sync(0xffffffffu, sr, m);
            sz += __shfl_xor_sync(0xffffffffu, sz, m);
            sn += __shfl_xor_sync(0xffffffffu, sn, m);
            sp += __shfl_xor_sync(0xffffffffu, sp, m);
        }

        // ---- phase C: gates (all lanes), tagged relaxed store ----
        float f0p = (t > 0) ? (sp + pb) : 0.f;
        float rr = fast_sig(gbr + f0p * wf0r + sr + b_r);
        float zz = fast_sig(gbz + f0p * wf0z + sz + b_z);
        float nn = fast_tanh(gbn + f0p * wf0n + rr * (sn + b_n));
        float hn = (1.f - zz) * nn + zz * hprev;
        hprev = hn;
        if (lane == 0) {
            ull pk = ((ull)(unsigned)(t + 1) << 32) | (ull)__float_as_uint(hn);
            st_rlx64(&g_ht[(t + 1) & 1][d], pk);
            if (d == 0 && t > 0) out[t - 1] = f0p;
        }
    }

    // ---- epilogue: f0(L-1) from h(L) (tag L in buf 0) ----
    if (cta == 0 && w == 0) {
        const unsigned tg = (unsigned)L_STEPS;
        ull ap = 0ull;
        #pragma unroll
        for (int k = 0; k < 16; ++k) {
            const ull* p0 = &g_ht[0][0] + 64 * k + 2 * lane;
            ull a = ld_rlx64(p0);
            while ((unsigned)(a >> 32) != tg) a = ld_rlx64(p0);
            ull b = ld_rlx64(p0 + 1);
            while ((unsigned)(b >> 32) != tg) b = ld_rlx64(p0 + 1);
            F2u hv; hv.f.x = __uint_as_float((unsigned)a);
                    hv.f.y = __uint_as_float((unsigned)b);
            ap = ffma2(wp[k], hv.u, ap);
        }
        F2u u; u.u = ap; float sp = u.f.x + u.f.y;
        #pragma unroll
        for (int m = 16; m >= 1; m >>= 1)
            sp += __shfl_xor_sync(0xffffffffu, sp, m);
        if (lane == 0) out[L_STEPS - 1] = sp + pb;
    }
}

// ---------------------------------------------------------------- launch
extern "C" void kernel_launch(void* const* d_in, const int* in_sizes, int n_in,
                              void* d_out, int out_size) {
    (void)in_sizes; (void)n_in; (void)out_size;
    const int*   vowel = (const int*)d_in[1];
    const int*   cons  = (const int*)d_in[2];
    const int*   sa    = (const int*)d_in[3];
    const int*   ea    = (const int*)d_in[4];
    const int*   sap   = (const int*)d_in[5];
    const int*   eap   = (const int*)d_in[6];
    const int*   sid   = (const int*)d_in[7];
    const float* emb   = (const float*)d_in[8];
    const float* spke  = (const float*)d_in[9];
    const float* encW  = (const float*)d_in[10];
    const float* encb  = (const float*)d_in[11];
    const float* Wih   = (const float*)d_in[12];
    const float* Whh   = (const float*)d_in[13];
    const float* bih   = (const float*)d_in[14];
    const float* bhh   = (const float*)d_in[15];
    const float* postW = (const float*)d_in[16];
    const float* postb = (const float*)d_in[17];
    float* out = (float*)d_out;

    k0_pack<<<L_STEPS / 256, 256>>>(vowel, cons, sa, ea, sap, eap);
    k1a_U<<<1024, 64>>>(encW, encb, emb, spke, sid);
    k1b_V<<<96, 256>>>(Wih);
    k3_scan<<<NCTA, 256>>>(Wih, Whh, bih, bhh, postW, postb, out);
}